// round 13
// baseline (speedup 1.0000x reference)
#include <cuda_runtime.h>

typedef unsigned long long u64;

#define Bsz 1024
#define Tn  128

__device__ __forceinline__ void fma2(u64 &d, u64 a, u64 b) {
    asm("fma.rn.f32x2 %0, %1, %2, %0;" : "+l"(d) : "l"(a), "l"(b));
}
__device__ __forceinline__ u64 add2(u64 a, u64 b) {
    u64 r; asm("add.rn.f32x2 %0, %1, %2;" : "=l"(r) : "l"(a), "l"(b)); return r;
}
__device__ __forceinline__ u64 mul2(u64 a, u64 b) {
    u64 r; asm("mul.rn.f32x2 %0, %1, %2;" : "=l"(r) : "l"(a), "l"(b)); return r;
}
__device__ __forceinline__ u64 pk2(float x) {
    u64 r; unsigned xi = __float_as_uint(x);
    asm("mov.b64 %0, {%1, %2};" : "=l"(r) : "r"(xi), "r"(xi));
    return r;
}
__device__ __forceinline__ u64 pkf2(float a, float b) {
    return (u64)__float_as_uint(a) | ((u64)__float_as_uint(b) << 32);
}
__device__ __forceinline__ float2 upk(u64 v) {
    unsigned lo, hi;
    asm("mov.b64 {%0, %1}, %2;" : "=r"(lo), "=r"(hi) : "l"(v));
    return make_float2(__uint_as_float(lo), __uint_as_float(hi));
}
// decode 2 biased-u16 ints packed in u32 -> packed f32x2 integer values
#define MAGIC2 0xCB008000CB008000ull   // packed (-8421376.f, -8421376.f)
__device__ __forceinline__ u64 dec16(unsigned w2) {
    unsigned lo, hi;
    asm("prmt.b32 %0, %1, %2, 0x4510;" : "=r"(lo) : "r"(w2), "r"(0x4Bu));
    asm("prmt.b32 %0, %1, %2, 0x4532;" : "=r"(hi) : "r"(w2), "r"(0x4Bu));
    u64 p; asm("mov.b64 %0, {%1, %2};" : "=l"(p) : "r"(lo), "r"(hi));
    return add2(p, MAGIC2);
}
// fast-math activations (validated R5-R12: tolerance 1e-3)
__device__ __forceinline__ float eluf(float x)  { return x > 0.f ? x : (__expf(x) - 1.f); }
__device__ __forceinline__ float sigf(float x)  { return __fdividef(1.f, 1.f + __expf(-x)); }
__device__ __forceinline__ float tanf_(float x) {
    x = fminf(fmaxf(x, -20.f), 20.f);
    float t = __expf(2.f * x);
    return __fdividef(t - 1.f, t + 1.f);
}
__device__ __forceinline__ float clipf(float x) { return fminf(fmaxf(x, -7.f), 5.f); }

// ---- weight scratch (zero-init; padded for prefetch overrun) --------------
// WbigQ: [k(264 pad)][n(1280)] u16 = round(Wfused[k][n]/s_col)+32768
__device__ unsigned short g_WbigQ[264 * 1280];
__device__ float g_cscale[1280];
// Wpq2: [kp][u(64)][4]: [2j+c] = Wstats[2(u&31)+c][2kp+j] (u<32 P, else Q)
__device__ float g_Wpq2 [128 * 64 * 4];
// Wih2: [kp][p(384)][4]
__device__ float g_Wih2 [20 * 384 * 4];
// emb weights [k][n], padded rows
__device__ float g_We1  [72 * 256];
__device__ float g_We2  [264 * 256];
__device__ float g_Wq1e [264 * 256];
__device__ float g_q1emb[(long)Bsz * Tn * 256];

// ---------------------------------------------------------------------------
__global__ void prepQ1(const float* __restrict__ Wp1, const float* __restrict__ Wq1,
                       const float* __restrict__ Whh)
{
    int n = blockIdx.x * blockDim.x + threadIdx.x;
    if (n >= 1280) return;
    float m = 0.f;
    for (int k = 0; k < 256; k++) {
        float v = (n < 256) ? Wp1[n * 256 + k]
                : (n < 512) ? Wq1[(n - 256) * 512 + k]
                            : Whh[(n - 512) * 256 + k];
        m = fmaxf(m, fabsf(v));
    }
    g_cscale[n] = fmaxf(m, 1e-30f) * (1.f / 32767.f);
}

__global__ void prep_kernel(const float* __restrict__ Wp1, const float* __restrict__ Wq1,
                            const float* __restrict__ Whh, const float* __restrict__ Wih,
                            const float* __restrict__ Wp2, const float* __restrict__ Wq2,
                            const float* __restrict__ We1, const float* __restrict__ We2)
{
    int tid = blockIdx.x * blockDim.x + threadIdx.x;
    int nt  = gridDim.x * blockDim.x;
    for (int i = tid; i < 256 * 1280; i += nt) {
        int k = i / 1280, n = i % 1280;
        float v = (n < 256) ? Wp1[n * 256 + k]
                : (n < 512) ? Wq1[(n - 256) * 512 + k]
                            : Whh[(n - 512) * 256 + k];
        int qv = __float2int_rn(v / g_cscale[n]);
        qv = max(-32767, min(32767, qv));
        g_WbigQ[k * 1280 + n] = (unsigned short)(qv + 32768);
    }
    for (int i = tid; i < 128 * 64 * 4; i += nt) {
        int c = i & 1, j = (i >> 1) & 1;
        int u = (i >> 2) & 63, kp = i >> 8;
        int k = 2 * kp + j, col = 2 * (u & 31) + c;
        g_Wpq2[i] = (u < 32) ? Wp2[col * 256 + k] : Wq2[col * 256 + k];
    }
    for (int i = tid; i < 20 * 384 * 4; i += nt) {
        int c = i & 1, j = (i >> 1) & 1;
        int p = (i >> 2) % 384, kp = i / 1536;
        g_Wih2[i] = Wih[(2 * p + c) * 40 + (2 * kp + j)];
    }
    for (int i = tid; i < 64 * 256; i += nt) {
        int k = i / 256, n = i % 256;
        g_We1[i] = We1[n * 64 + k];
    }
    for (int i = tid; i < 256 * 256; i += nt) {
        int k = i / 256, n = i % 256;
        g_We2[i]  = We2[n * 256 + k];
        g_Wq1e[i] = Wq1[n * 512 + 256 + k];
    }
}

// ---------------------------------------------------------------------------
// emb: 4096 CTAs x 32 rows, 512 threads (unchanged)
// ---------------------------------------------------------------------------
#define EMB_T 512
#define EMB_SMEM ((32*64 + 2*32*256) * 8)

__device__ __forceinline__ void gemm256(u64 acc[4][2], const u64* in_dup,
                                        const float* Wg, int p, int r0)
{
    const ulonglong2* W = (const ulonglong2*)Wg;   // [k][64]
    #pragma unroll
    for (int r = 0; r < 4; r++) { acc[r][0] = 0ull; acc[r][1] = 0ull; }
    ulonglong2 wc0 = W[p], wc1 = W[64 + p], wc2 = W[128 + p], wc3 = W[192 + p];
    for (int kb = 0; kb < 256; kb += 4) {
        int nb = (kb + 4) * 64 + p;
        ulonglong2 wn0 = W[nb], wn1 = W[nb + 64], wn2 = W[nb + 128], wn3 = W[nb + 192];
        #pragma unroll
        for (int r = 0; r < 4; r++) {
            const ulonglong2* Hb = (const ulonglong2*)(in_dup + (long)(r0 + r) * 256) + (kb >> 1);
            ulonglong2 h01 = Hb[0], h23 = Hb[1];
            fma2(acc[r][0], h01.x, wc0.x); fma2(acc[r][1], h01.x, wc0.y);
            fma2(acc[r][0], h01.y, wc1.x); fma2(acc[r][1], h01.y, wc1.y);
            fma2(acc[r][0], h23.x, wc2.x); fma2(acc[r][1], h23.x, wc2.y);
            fma2(acc[r][0], h23.y, wc3.x); fma2(acc[r][1], h23.y, wc3.y);
        }
        wc0 = wn0; wc1 = wn1; wc2 = wn2; wc3 = wn3;
    }
}

__global__ void __launch_bounds__(EMB_T, 1) emb_kernel(
    const float* __restrict__ obs, const float* __restrict__ be1,
    const float* __restrict__ be2, const float* __restrict__ bq1)
{
    extern __shared__ u64 smu[];
    u64* obs2 = smu;               // 32*64
    u64* e1   = smu + 32 * 64;     // 32*256
    u64* e2   = e1 + 32 * 256;     // 32*256

    int t    = threadIdx.x;
    int row0 = blockIdx.x * 32;
    int p    = t & 63;
    int r0   = (t >> 6) * 4;

    for (int i = t; i < 32 * 64; i += EMB_T)
        obs2[i] = pk2(__ldcs(&obs[(long)row0 * 64 + i]));

    float4 b1 = *(const float4*)&be1[4 * p];
    float4 b2 = *(const float4*)&be2[4 * p];
    float4 bq = *(const float4*)&bq1[4 * p];
    __syncthreads();

    u64 acc[4][2];

    // stage 1: K=64 obs -> e1
    {
        const ulonglong2* W = (const ulonglong2*)g_We1;
        #pragma unroll
        for (int r = 0; r < 4; r++) { acc[r][0] = 0ull; acc[r][1] = 0ull; }
        ulonglong2 wc0 = W[p], wc1 = W[64 + p], wc2 = W[128 + p], wc3 = W[192 + p];
        for (int kb = 0; kb < 64; kb += 4) {
            int nb = (kb + 4) * 64 + p;
            ulonglong2 wn0 = W[nb], wn1 = W[nb + 64], wn2 = W[nb + 128], wn3 = W[nb + 192];
            #pragma unroll
            for (int r = 0; r < 4; r++) {
                const ulonglong2* Hb = (const ulonglong2*)(obs2 + (long)(r0 + r) * 64) + (kb >> 1);
                ulonglong2 h01 = Hb[0], h23 = Hb[1];
                fma2(acc[r][0], h01.x, wc0.x); fma2(acc[r][1], h01.x, wc0.y);
                fma2(acc[r][0], h01.y, wc1.x); fma2(acc[r][1], h01.y, wc1.y);
                fma2(acc[r][0], h23.x, wc2.x); fma2(acc[r][1], h23.x, wc2.y);
                fma2(acc[r][0], h23.y, wc3.x); fma2(acc[r][1], h23.y, wc3.y);
            }
            wc0 = wn0; wc1 = wn1; wc2 = wn2; wc3 = wn3;
        }
        #pragma unroll
        for (int r = 0; r < 4; r++) {
            float2 a0 = upk(acc[r][0]), a1 = upk(acc[r][1]);
            ulonglong2* E = (ulonglong2*)(e1 + (long)(r0 + r) * 256 + 4 * p);
            E[0] = make_ulonglong2(pk2(eluf(a0.x + b1.x)), pk2(eluf(a0.y + b1.y)));
            E[1] = make_ulonglong2(pk2(eluf(a1.x + b1.z)), pk2(eluf(a1.y + b1.w)));
        }
    }
    __syncthreads();

    gemm256(acc, e1, g_We2, p, r0);
    #pragma unroll
    for (int r = 0; r < 4; r++) {
        float2 a0 = upk(acc[r][0]), a1 = upk(acc[r][1]);
        ulonglong2* E = (ulonglong2*)(e2 + (long)(r0 + r) * 256 + 4 * p);
        E[0] = make_ulonglong2(pk2(eluf(a0.x + b2.x)), pk2(eluf(a0.y + b2.y)));
        E[1] = make_ulonglong2(pk2(eluf(a1.x + b2.z)), pk2(eluf(a1.y + b2.w)));
    }
    __syncthreads();

    gemm256(acc, e2, g_Wq1e, p, r0);
    #pragma unroll
    for (int r = 0; r < 4; r++) {
        float2 a0 = upk(acc[r][0]), a1 = upk(acc[r][1]);
        float4 v = make_float4(a0.x + bq.x, a0.y + bq.y, a1.x + bq.z, a1.y + bq.w);
        __stcs((float4*)&g_q1emb[(long)(row0 + r0 + r) * 256 + 4 * p], v);
    }
}

// ---------------------------------------------------------------------------
// seq: 256 CTAs x 4 rows, 320 threads, occupancy 2.
// S1 weights int16 + per-column scale; decode via PRMT + packed add; scale in
// epilogue. kh = k-half (p>=160), qi = col-octet: 8 cols x 4 rows x 128 k.
// ---------------------------------------------------------------------------
#define SQ_T 320
// u64: h2 1024 | G1p 1024 | G1q 1024 | x2 160 | part 2560 = 5792
// float: Gh 3072 | gi 3072 | qb 2048 = 8192
#define SEQ_SMEM (5792*8 + 8192*4)

__global__ void __launch_bounds__(SQ_T, 2) seq_kernel(
    const float* __restrict__ act,  const float* __restrict__ noise,
    const float* __restrict__ b_p1, const float* __restrict__ b_hh,
    const float* __restrict__ b_p2, const float* __restrict__ b_q2,
    const float* __restrict__ b_ih, float* __restrict__ out)
{
    extern __shared__ u64 smu[];
    u64* h2   = smu;             // [1024] dup h (4 rows x 256)
    u64* G1p  = smu + 1024;      // [1024]
    u64* G1q  = smu + 2048;      // [1024]
    u64* x2   = smu + 3072;      // [160]
    u64* part = smu + 3232;      // [2560]
    float* Gh = (float*)(smu + 5792);   // [3072]
    float* gi = Gh + 3072;              // [3072]
    float* qb = gi + 3072;              // [2][1024]
    float* hF = (float*)h2;

    int p  = threadIdx.x;
    int b0 = blockIdx.x * 4;

    int kh  = (p >= 160);
    int qi  = p - (kh ? 160 : 0);   // 0..159
    int n0  = 8 * qi;
    int r0e = 2 * kh;               // epilogue rows r0e, r0e+1

    for (int i = p; i < 1024; i += SQ_T) h2[i] = 0ull;
    if (p < 256) {                  // initial q1emb (t=0)
        int r = p >> 6, c4 = (p & 63) * 4;
        *(float4*)&qb[r * 256 + c4] =
            __ldcs((const float4*)&g_q1emb[(long)(b0 + r) * Tn * 256 + c4]);
    }

    // per-column scales for this thread's 8 cols (as packed pairs)
    u64 sc[4];
    {
        float4 sa = *(const float4*)&g_cscale[n0];
        float4 sb = *(const float4*)&g_cscale[n0 + 4];
        sc[0] = pkf2(sa.x, sa.y); sc[1] = pkf2(sa.z, sa.w);
        sc[2] = pkf2(sb.x, sb.y); sc[3] = pkf2(sb.z, sb.w);
    }

    float4 b1a = make_float4(0.f, 0.f, 0.f, 0.f), b1b = b1a;
    if (n0 < 256) {
        b1a = *(const float4*)&b_p1[n0]; b1b = *(const float4*)&b_p1[n0 + 4];
    } else if (n0 >= 512) {
        b1a = *(const float4*)&b_hh[n0 - 512]; b1b = *(const float4*)&b_hh[n0 - 508];
    }

    int s2_u = p & 63, s2_kb = p >> 6;   // valid for p<256
    int s2_c = s2_u & 31;
    float2 s2_b = make_float2(0.f, 0.f);
    if (p < 256) s2_b = (s2_u < 32) ? *(const float2*)&b_p2[2 * s2_c]
                                    : *(const float2*)&b_q2[2 * s2_c];
    __syncthreads();

    const ulonglong2* WPQ = (const ulonglong2*)g_Wpq2;    // [kp][64]
    const ulonglong2* WI  = (const ulonglong2*)g_Wih2;    // [kp][384]
    const ulonglong2* H2v = (const ulonglong2*)h2;        // [4][128]
    const ulonglong2* X2v = (const ulonglong2*)x2;        // [4][20]
    const uint4* Wq = (const uint4*)g_WbigQ + (kh ? 128 * 160 : 0) + qi; // [k][160]
    const ulonglong2* Hb = H2v + kh * 64;                 // + r*128 + it

    for (int tt = 0; tt < Tn; tt++) {
        const float* qcur = qb + (tt & 1) * 1024;
        float*       qnxt = qb + ((tt + 1) & 1) * 1024;

        // --- prefetch (consumed in fused S2 phase) ---
        float2 eps = make_float2(0.f, 0.f);
        float  av  = 0.f;
        if (p < 256 && s2_u >= 32 && s2_u < 48) {
            int r = p >> 6, c = s2_u - 32;
            eps = __ldcs((const float2*)&noise[(long)tt * 32768 + (b0 + r) * 32 + 2 * c]);
        } else if (p >= 288) {
            int qq = p - 288, r = qq >> 3, j = qq & 7;
            av = __ldcs(&act[(long)(b0 + r) * 1024 + tt * 8 + j]);
        }

        // ===== S1: int16 weights, 8 cols x 4 rows x 128 k (half kh) =====
        u64 acc[4][4];
        #pragma unroll
        for (int r = 0; r < 4; r++)
            #pragma unroll
            for (int c = 0; c < 4; c++) acc[r][c] = 0ull;
        {
            uint4 wa = Wq[0], wb = Wq[160];
            for (int it = 0; it < 64; it++) {
                const uint4* Wn = Wq + (2 * it + 2) * 160;
                uint4 na = Wn[0], nb = Wn[160];
                u64 wA0 = dec16(wa.x), wA1 = dec16(wa.y),
                    wA2 = dec16(wa.z), wA3 = dec16(wa.w);
                u64 wB0 = dec16(wb.x), wB1 = dec16(wb.y),
                    wB2 = dec16(wb.z), wB3 = dec16(wb.w);
                #pragma unroll
                for (int r = 0; r < 4; r++) {
                    ulonglong2 h01 = Hb[r * 128 + it];
                    fma2(acc[r][0], h01.x, wA0); fma2(acc[r][1], h01.x, wA1);
                    fma2(acc[r][2], h01.x, wA2); fma2(acc[r][3], h01.x, wA3);
                    fma2(acc[r][0], h01.y, wB0); fma2(acc[r][1], h01.y, wB1);
                    fma2(acc[r][2], h01.y, wB2); fma2(acc[r][3], h01.y, wB3);
                }
                wa = na; wb = nb;
            }
        }
        // store partials of the OTHER half's epilogue rows (unscaled)
        {
            #pragma unroll
            for (int rr = 0; rr < 2; rr++) {
                int orow = 2 * (1 - kh) + rr;
                ulonglong2* P = (ulonglong2*)&part[((kh * 2 + rr) * 160 + qi) * 4];
                P[0] = make_ulonglong2(acc[orow][0], acc[orow][1]);
                P[1] = make_ulonglong2(acc[orow][2], acc[orow][3]);
            }
        }
        __syncthreads();

        // ===== S1 reduce + scale + epilogue (rows r0e, r0e+1) =====
        {
            u64 fin[2][4];
            #pragma unroll
            for (int rr = 0; rr < 2; rr++) {
                const ulonglong2* P = (const ulonglong2*)
                    &part[(((1 - kh) * 2 + rr) * 160 + qi) * 4];
                ulonglong2 p0 = P[0], p1 = P[1];
                fin[rr][0] = mul2(add2(acc[r0e + rr][0], p0.x), sc[0]);
                fin[rr][1] = mul2(add2(acc[r0e + rr][1], p0.y), sc[1]);
                fin[rr][2] = mul2(add2(acc[r0e + rr][2], p1.x), sc[2]);
                fin[rr][3] = mul2(add2(acc[r0e + rr][3], p1.y), sc[3]);
            }
            #pragma unroll
            for (int rr = 0; rr < 2; rr++) {
                int row = r0e + rr;
                float2 a0 = upk(fin[rr][0]), a1 = upk(fin[rr][1]);
                float2 a2 = upk(fin[rr][2]), a3 = upk(fin[rr][3]);
                if (n0 < 256) {
                    ulonglong2* E = (ulonglong2*)(G1p + row * 256 + n0);
                    E[0] = make_ulonglong2(pk2(eluf(a0.x + b1a.x)), pk2(eluf(a0.y + b1a.y)));
                    E[1] = make_ulonglong2(pk2(eluf(a1.x + b1a.z)), pk2(eluf(a1.y + b1a.w)));
                    E[2] = make_ulonglong2(pk2(eluf(a2.x + b1b.x)), pk2(eluf(a2.y + b1b.y)));
                    E[3] = make_ulonglong2(pk2(eluf(a3.x + b1b.z)), pk2(eluf(a3.y + b1b.w)));
                } else if (n0 < 512) {
                    float4 q0 = *(const float4*)&qcur[row * 256 + (n0 - 256)];
                    float4 q1 = *(const float4*)&qcur[row * 256 + (n0 - 252)];
                    ulonglong2* E = (ulonglong2*)(G1q + row * 256 + (n0 - 256));
                    E[0] = make_ulonglong2(pk2(eluf(a0.x + q0.x)), pk2(eluf(a0.y + q0.y)));
                    E[1] = make_ulonglong2(pk2(eluf(a1.x + q0.z)), pk2(eluf(a1.y + q0.w)));
                    E[2] = make_ulonglong2(pk2(eluf(a2.x + q1.x)), pk2(eluf(a2.y + q1.y)));
                    E[3] = make_ulonglong2(pk2(eluf(a3.x + q1.z)), pk2(eluf(a3.y + q1.w)));
                } else {
                    *(float4*)&Gh[row * 768 + (n0 - 512)] =
                        make_float4(a0.x + b1a.x, a0.y + b1a.y, a1.x + b1a.z, a1.y + b1a.w);
                    *(float4*)&Gh[row * 768 + (n0 - 508)] =
                        make_float4(a2.x + b1b.x, a2.y + b1b.y, a3.x + b1b.z, a3.y + b1b.w);
                }
            }
        }
        __syncthreads();

        // ==== S2 partials (p<256); p>=256: h-out + next-q1emb prefetch ====
        if (p < 256) {
            const ulonglong2* INv = (const ulonglong2*)((s2_u < 32) ? G1p : G1q);
            u64 a4[4];
            #pragma unroll
            for (int r = 0; r < 4; r++) a4[r] = 0ull;
            int kbase = s2_kb * 32;
            #pragma unroll 4
            for (int qq2 = 0; qq2 < 32; qq2++) {
                int kpg = kbase + qq2;
                ulonglong2 w = WPQ[kpg * 64 + s2_u];
                #pragma unroll
                for (int r = 0; r < 4; r++) {
                    ulonglong2 iv = INv[r * 128 + kpg];
                    fma2(a4[r], iv.x, w.x);
                    fma2(a4[r], iv.y, w.y);
                }
            }
            #pragma unroll
            for (int r = 0; r < 4; r++)
                part[(s2_kb * 4 + r) * 64 + s2_u] = a4[r];
        } else {
            int idx = p - 256;   // 0..63
            #pragma unroll
            for (int j = 0; j < 16; j++) {
                int i = idx + j * 64, r = i >> 8, d = i & 255;
                __stcs(&out[(long)(b0 + r) * 53248 + tt * 416 + d], hF[2 * i]);
            }
            if (tt + 1 < Tn) {
                #pragma unroll
                for (int j = 0; j < 4; j++) {
                    int i = idx + j * 64;            // 0..255 float4 chunks
                    int r = i >> 6, c4 = (i & 63) * 4;
                    *(float4*)&qnxt[r * 256 + c4] =
                        __ldcs((const float4*)&g_q1emb[((long)(b0 + r) * Tn + tt + 1) * 256 + c4]);
                }
            }
        }
        __syncthreads();

        // ===== Fused S2 reduce: stats -> out, z via shfl, x2 =====
        if (p < 256) {
            int r = p >> 6;
            u64 s = part[r * 64 + s2_u];
            #pragma unroll
            for (int kb = 1; kb < 4; kb++)
                s = add2(s, part[(kb * 4 + r) * 64 + s2_u]);
            float2 v = upk(s);
            v.x += s2_b.x; v.y += s2_b.y;
            if (s2_c >= 16) { v.x = __expf(clipf(v.x)); v.y = __expf(clipf(v.y)); }
            long ob = (long)(b0 + r) * 53248 + tt * 416;
            __stcs((float2*)&out[ob + 288 + (s2_u < 32 ? 0 : 64) + 2 * s2_c], v);
            if (s2_u >= 32) {   // Q warps: swap qm<->qs across half-warps
                float ox = __shfl_xor_sync(0xffffffffu, v.x, 16);
                float oy = __shfl_xor_sync(0xffffffffu, v.y, 16);
                if (s2_c < 16) {
                    float z0 = fmaf(ox, eps.x, v.x);
                    float z1 = fmaf(oy, eps.y, v.y);
                    *(ulonglong2*)&x2[r * 40 + 2 * s2_c] =
                        make_ulonglong2(pk2(z0), pk2(z1));
                    __stcs((float2*)&out[ob + 256 + 2 * s2_c], make_float2(z0, z1));
                }
            }
        } else if (p >= 288) {
            int qq = p - 288, r = qq >> 3, j = qq & 7;
            x2[r * 40 + 32 + j] = pk2(av);
        }
        __syncthreads();

        // ===== S3: gi = x @ W_ih (384 col-pairs over 320 threads) =====
        for (int cp = p; cp < 384; cp += SQ_T) {
            float2 bih = *(const float2*)&b_ih[2 * cp];
            u64 a3[4];
            #pragma unroll
            for (int r = 0; r < 4; r++) a3[r] = 0ull;
            #pragma unroll 4
            for (int kp = 0; kp < 20; kp++) {
                ulonglong2 w = WI[kp * 384 + cp];
                #pragma unroll
                for (int r = 0; r < 4; r++) {
                    ulonglong2 iv = X2v[r * 20 + kp];
                    fma2(a3[r], iv.x, w.x);
                    fma2(a3[r], iv.y, w.y);
                }
            }
            #pragma unroll
            for (int r = 0; r < 4; r++) {
                float2 a0 = upk(a3[r]);
                *(float2*)&gi[r * 768 + 2 * cp] = make_float2(a0.x + bih.x, a0.y + bih.y);
            }
        }
        __syncthreads();

        // ===== S4: GRU gates -> new h =====
        for (int i = p; i < 1024; i += SQ_T) {
            int r = i >> 8, d = i & 255;
            float gir = gi[r * 768 + d];
            float giz = gi[r * 768 + 256 + d];
            float gin = gi[r * 768 + 512 + d];
            float ghr = Gh[r * 768 + d];
            float ghz = Gh[r * 768 + 256 + d];
            float ghn = Gh[r * 768 + 512 + d];
            float rg = sigf(gir + ghr);
            float ug = sigf(giz + ghz);
            float ng = tanf_(gin + rg * ghn);
            float ho = hF[2 * i];
            h2[i] = pk2((1.f - ug) * ng + ug * ho);
        }
        __syncthreads();
    }
}

// ---------------------------------------------------------------------------
extern "C" void kernel_launch(void* const* d_in, const int* in_sizes, int n_in,
                              void* d_out, int out_size)
{
    const float* obs = (const float*)d_in[0];
    const float* act = (const float*)d_in[1];
    const float* noi = (const float*)d_in[2];
    const float* We1 = (const float*)d_in[3];
    const float* be1 = (const float*)d_in[4];
    const float* We2 = (const float*)d_in[5];
    const float* be2 = (const float*)d_in[6];
    const float* Wih = (const float*)d_in[7];
    const float* Whh = (const float*)d_in[8];
    const float* bih = (const float*)d_in[9];
    const float* bhh = (const float*)d_in[10];
    const float* Wp1 = (const float*)d_in[11];
    const float* bp1 = (const float*)d_in[12];
    const float* Wp2 = (const float*)d_in[13];
    const float* bp2 = (const float*)d_in[14];
    const float* Wq1 = (const float*)d_in[15];
    const float* bq1 = (const float*)d_in[16];
    const float* Wq2 = (const float*)d_in[17];
    const float* bq2 = (const float*)d_in[18];
    float* out = (float*)d_out;

    cudaFuncSetAttribute(emb_kernel, cudaFuncAttributeMaxDynamicSharedMemorySize, EMB_SMEM);
    cudaFuncSetAttribute(seq_kernel, cudaFuncAttributeMaxDynamicSharedMemorySize, SEQ_SMEM);

    prepQ1<<<5, 256>>>(Wp1, Wq1, Whh);
    prep_kernel<<<64, 256>>>(Wp1, Wq1, Whh, Wih, Wp2, Wq2, We1, We2);
    emb_kernel<<<(Bsz * Tn) / 32, EMB_T, EMB_SMEM>>>(obs, be1, be2, bq1);
    seq_kernel<<<Bsz / 4, SQ_T, SEQ_SMEM>>>(act, noi, bp1, bhh, bp2, bq2, bih, out);
}

// round 14
// speedup vs baseline: 1.1982x; 1.1982x over previous
#include <cuda_runtime.h>

typedef unsigned long long u64;

#define Bsz 1024
#define Tn  128

__device__ __forceinline__ void fma2(u64 &d, u64 a, u64 b) {
    asm("fma.rn.f32x2 %0, %1, %2, %0;" : "+l"(d) : "l"(a), "l"(b));
}
__device__ __forceinline__ u64 add2(u64 a, u64 b) {
    u64 r; asm("add.rn.f32x2 %0, %1, %2;" : "=l"(r) : "l"(a), "l"(b)); return r;
}
__device__ __forceinline__ u64 pk2(float x) {
    u64 r; unsigned xi = __float_as_uint(x);
    asm("mov.b64 %0, {%1, %2};" : "=l"(r) : "r"(xi), "r"(xi));
    return r;
}
__device__ __forceinline__ float2 upk(u64 v) {
    unsigned lo, hi;
    asm("mov.b64 {%0, %1}, %2;" : "=r"(lo), "=r"(hi) : "l"(v));
    return make_float2(__uint_as_float(lo), __uint_as_float(hi));
}
// fast-math activations (validated R5-R12: tolerance 1e-3)
__device__ __forceinline__ float eluf(float x)  { return x > 0.f ? x : (__expf(x) - 1.f); }
__device__ __forceinline__ float sigf(float x)  { return __fdividef(1.f, 1.f + __expf(-x)); }
__device__ __forceinline__ float tanf_(float x) {
    x = fminf(fmaxf(x, -20.f), 20.f);
    float t = __expf(2.f * x);
    return __fdividef(t - 1.f, t + 1.f);
}
__device__ __forceinline__ float clipf(float x) { return fminf(fmaxf(x, -7.f), 5.f); }

// ---- weight scratch (zero-init; padded for prefetch overrun) --------------
// Wbig8: [kp][s(4)][qi(160)][4f]: slot s: j=s>>1 (k=2kp+j), c=(s&1)*4+e
__device__ float g_Wbig8[132 * 160 * 16];
// Wpq2: [kp][u(64)][4]
__device__ float g_Wpq2 [128 * 64 * 4];
// Wih2: [kp][p(384)][4]
__device__ float g_Wih2 [20 * 384 * 4];
// emb weights [k][n], padded rows
__device__ float g_We1  [72 * 256];
__device__ float g_We2  [264 * 256];
__device__ float g_Wq1e [264 * 256];
__device__ float g_q1emb[(long)Bsz * Tn * 256];

// ---------------------------------------------------------------------------
__global__ void prep_kernel(const float* __restrict__ Wp1, const float* __restrict__ Wq1,
                            const float* __restrict__ Whh, const float* __restrict__ Wih,
                            const float* __restrict__ Wp2, const float* __restrict__ Wq2,
                            const float* __restrict__ We1, const float* __restrict__ We2)
{
    int tid = blockIdx.x * blockDim.x + threadIdx.x;
    int nt  = gridDim.x * blockDim.x;
    for (int i = tid; i < 128 * 2560; i += nt) {
        int kp = i / 2560, rem = i % 2560;
        int s = rem / 640, rem2 = rem % 640;
        int qi = rem2 >> 2, e = rem2 & 3;
        int j = s >> 1, c = (s & 1) * 4 + e;
        int k = 2 * kp + j, n = 8 * qi + c;
        float v;
        if (n < 256)      v = Wp1[n * 256 + k];
        else if (n < 512) v = Wq1[(n - 256) * 512 + k];
        else              v = Whh[(n - 512) * 256 + k];
        g_Wbig8[i] = v;
    }
    for (int i = tid; i < 128 * 64 * 4; i += nt) {
        int c = i & 1, j = (i >> 1) & 1;
        int u = (i >> 2) & 63, kp = i >> 8;
        int k = 2 * kp + j, col = 2 * (u & 31) + c;
        g_Wpq2[i] = (u < 32) ? Wp2[col * 256 + k] : Wq2[col * 256 + k];
    }
    for (int i = tid; i < 20 * 384 * 4; i += nt) {
        int c = i & 1, j = (i >> 1) & 1;
        int p = (i >> 2) % 384, kp = i / 1536;
        g_Wih2[i] = Wih[(2 * p + c) * 40 + (2 * kp + j)];
    }
    for (int i = tid; i < 64 * 256; i += nt) {
        int k = i / 256, n = i % 256;
        g_We1[i] = We1[n * 64 + k];
    }
    for (int i = tid; i < 256 * 256; i += nt) {
        int k = i / 256, n = i % 256;
        g_We2[i]  = We2[n * 256 + k];
        g_Wq1e[i] = Wq1[n * 512 + 256 + k];
    }
}

// ---------------------------------------------------------------------------
// emb: 4096 CTAs x 32 rows, 512 threads (unchanged from R12)
// ---------------------------------------------------------------------------
#define EMB_T 512
#define EMB_SMEM ((32*64 + 2*32*256) * 8)

__device__ __forceinline__ void gemm256(u64 acc[4][2], const u64* in_dup,
                                        const float* Wg, int p, int r0)
{
    const ulonglong2* W = (const ulonglong2*)Wg;   // [k][64]
    #pragma unroll
    for (int r = 0; r < 4; r++) { acc[r][0] = 0ull; acc[r][1] = 0ull; }
    ulonglong2 wc0 = W[p], wc1 = W[64 + p], wc2 = W[128 + p], wc3 = W[192 + p];
    for (int kb = 0; kb < 256; kb += 4) {
        int nb = (kb + 4) * 64 + p;
        ulonglong2 wn0 = W[nb], wn1 = W[nb + 64], wn2 = W[nb + 128], wn3 = W[nb + 192];
        #pragma unroll
        for (int r = 0; r < 4; r++) {
            const ulonglong2* Hb = (const ulonglong2*)(in_dup + (long)(r0 + r) * 256) + (kb >> 1);
            ulonglong2 h01 = Hb[0], h23 = Hb[1];
            fma2(acc[r][0], h01.x, wc0.x); fma2(acc[r][1], h01.x, wc0.y);
            fma2(acc[r][0], h01.y, wc1.x); fma2(acc[r][1], h01.y, wc1.y);
            fma2(acc[r][0], h23.x, wc2.x); fma2(acc[r][1], h23.x, wc2.y);
            fma2(acc[r][0], h23.y, wc3.x); fma2(acc[r][1], h23.y, wc3.y);
        }
        wc0 = wn0; wc1 = wn1; wc2 = wn2; wc3 = wn3;
    }
}

__global__ void __launch_bounds__(EMB_T, 1) emb_kernel(
    const float* __restrict__ obs, const float* __restrict__ be1,
    const float* __restrict__ be2, const float* __restrict__ bq1)
{
    extern __shared__ u64 smu[];
    u64* obs2 = smu;               // 32*64
    u64* e1   = smu + 32 * 64;     // 32*256
    u64* e2   = e1 + 32 * 256;     // 32*256

    int t    = threadIdx.x;
    int row0 = blockIdx.x * 32;
    int p    = t & 63;
    int r0   = (t >> 6) * 4;

    for (int i = t; i < 32 * 64; i += EMB_T)
        obs2[i] = pk2(__ldcs(&obs[(long)row0 * 64 + i]));

    float4 b1 = *(const float4*)&be1[4 * p];
    float4 b2 = *(const float4*)&be2[4 * p];
    float4 bq = *(const float4*)&bq1[4 * p];
    __syncthreads();

    u64 acc[4][2];

    // stage 1: K=64 obs -> e1
    {
        const ulonglong2* W = (const ulonglong2*)g_We1;
        #pragma unroll
        for (int r = 0; r < 4; r++) { acc[r][0] = 0ull; acc[r][1] = 0ull; }
        ulonglong2 wc0 = W[p], wc1 = W[64 + p], wc2 = W[128 + p], wc3 = W[192 + p];
        for (int kb = 0; kb < 64; kb += 4) {
            int nb = (kb + 4) * 64 + p;
            ulonglong2 wn0 = W[nb], wn1 = W[nb + 64], wn2 = W[nb + 128], wn3 = W[nb + 192];
            #pragma unroll
            for (int r = 0; r < 4; r++) {
                const ulonglong2* Hb = (const ulonglong2*)(obs2 + (long)(r0 + r) * 64) + (kb >> 1);
                ulonglong2 h01 = Hb[0], h23 = Hb[1];
                fma2(acc[r][0], h01.x, wc0.x); fma2(acc[r][1], h01.x, wc0.y);
                fma2(acc[r][0], h01.y, wc1.x); fma2(acc[r][1], h01.y, wc1.y);
                fma2(acc[r][0], h23.x, wc2.x); fma2(acc[r][1], h23.x, wc2.y);
                fma2(acc[r][0], h23.y, wc3.x); fma2(acc[r][1], h23.y, wc3.y);
            }
            wc0 = wn0; wc1 = wn1; wc2 = wn2; wc3 = wn3;
        }
        #pragma unroll
        for (int r = 0; r < 4; r++) {
            float2 a0 = upk(acc[r][0]), a1 = upk(acc[r][1]);
            ulonglong2* E = (ulonglong2*)(e1 + (long)(r0 + r) * 256 + 4 * p);
            E[0] = make_ulonglong2(pk2(eluf(a0.x + b1.x)), pk2(eluf(a0.y + b1.y)));
            E[1] = make_ulonglong2(pk2(eluf(a1.x + b1.z)), pk2(eluf(a1.y + b1.w)));
        }
    }
    __syncthreads();

    gemm256(acc, e1, g_We2, p, r0);
    #pragma unroll
    for (int r = 0; r < 4; r++) {
        float2 a0 = upk(acc[r][0]), a1 = upk(acc[r][1]);
        ulonglong2* E = (ulonglong2*)(e2 + (long)(r0 + r) * 256 + 4 * p);
        E[0] = make_ulonglong2(pk2(eluf(a0.x + b2.x)), pk2(eluf(a0.y + b2.y)));
        E[1] = make_ulonglong2(pk2(eluf(a1.x + b2.z)), pk2(eluf(a1.y + b2.w)));
    }
    __syncthreads();

    gemm256(acc, e2, g_Wq1e, p, r0);
    #pragma unroll
    for (int r = 0; r < 4; r++) {
        float2 a0 = upk(acc[r][0]), a1 = upk(acc[r][1]);
        float4 v = make_float4(a0.x + bq.x, a0.y + bq.y, a1.x + bq.z, a1.y + bq.w);
        __stcs((float4*)&g_q1emb[(long)(row0 + r0 + r) * 256 + 4 * p], v);
    }
}

// ---------------------------------------------------------------------------
// seq: 296 CTAs (148x4row + 136x3row + 12x2row), 320 threads, occ 2.
// CTA b and b+148 share an SM -> every SM gets 4 + (3|2) rows = 7|6 (was 8|4).
// Body identical to R12 modulo NR guards.
// ---------------------------------------------------------------------------
#define SQ_T 320
#define SEQ_SMEM (5792*8 + 8192*4)

template<int NR>
__device__ __forceinline__ void seq_body(
    int b0, u64* smu,
    const float* __restrict__ act,  const float* __restrict__ noise,
    const float* __restrict__ b_p1, const float* __restrict__ b_hh,
    const float* __restrict__ b_p2, const float* __restrict__ b_q2,
    const float* __restrict__ b_ih, float* __restrict__ out)
{
    u64* h2   = smu;             // [1024] dup h (4 rows x 256; rows>=NR unused)
    u64* G1p  = smu + 1024;      // [1024]
    u64* G1q  = smu + 2048;      // [1024]
    u64* x2   = smu + 3072;      // [160]
    u64* part = smu + 3232;      // [2560]
    float* Gh = (float*)(smu + 5792);   // [3072]
    float* gi = Gh + 3072;              // [3072]
    float* qb = gi + 3072;              // [2][1024]
    float* hF = (float*)h2;

    int p = threadIdx.x;

    int kh  = (p >= 160);
    int qi  = p - (kh ? 160 : 0);   // 0..159
    int n0  = 8 * qi;
    int r0e = 2 * kh;               // epilogue rows r0e, r0e+1

    for (int i = p; i < 1024; i += SQ_T) h2[i] = 0ull;
    if (p < 256) {                  // initial q1emb (t=0)
        int r = p >> 6, c4 = (p & 63) * 4;
        if (r < NR)
            *(float4*)&qb[r * 256 + c4] =
                __ldcs((const float4*)&g_q1emb[(long)(b0 + r) * Tn * 256 + c4]);
    }

    float4 b1a = make_float4(0.f, 0.f, 0.f, 0.f), b1b = b1a;
    if (n0 < 256) {
        b1a = *(const float4*)&b_p1[n0]; b1b = *(const float4*)&b_p1[n0 + 4];
    } else if (n0 >= 512) {
        b1a = *(const float4*)&b_hh[n0 - 512]; b1b = *(const float4*)&b_hh[n0 - 508];
    }

    int s2_u = p & 63, s2_kb = p >> 6;   // valid for p<256
    int s2_c = s2_u & 31;
    float2 s2_b = make_float2(0.f, 0.f);
    if (p < 256) s2_b = (s2_u < 32) ? *(const float2*)&b_p2[2 * s2_c]
                                    : *(const float2*)&b_q2[2 * s2_c];
    __syncthreads();

    const ulonglong2* WPQ = (const ulonglong2*)g_Wpq2;    // [kp][64]
    const ulonglong2* WI  = (const ulonglong2*)g_Wih2;    // [kp][384]
    const ulonglong2* H2v = (const ulonglong2*)h2;        // [4][128]
    const ulonglong2* X2v = (const ulonglong2*)x2;        // [4][20]
    const ulonglong2* WQ  = (const ulonglong2*)g_Wbig8 + (long)kh * 64 * 640 + qi;
    const ulonglong2* Hb  = H2v + kh * 64;                // + r*128

    for (int tt = 0; tt < Tn; tt++) {
        const float* qcur = qb + (tt & 1) * 1024;
        float*       qnxt = qb + ((tt + 1) & 1) * 1024;

        // --- prefetch (consumed in fused S2 phase) ---
        float2 eps = make_float2(0.f, 0.f);
        float  av  = 0.f;
        if (p < 256 && s2_u >= 32 && s2_u < 48) {
            int r = p >> 6, c = s2_u - 32;
            if (r < NR)
                eps = __ldcs((const float2*)&noise[(long)tt * 32768 + (b0 + r) * 32 + 2 * c]);
        } else if (p >= 288) {
            int qq = p - 288, r = qq >> 3, j = qq & 7;
            if (r < NR)
                av = __ldcs(&act[(long)(b0 + r) * 1024 + tt * 8 + j]);
        }

        // ===== S1: 8 cols x NR rows over this thread's k-half =====
        u64 acc[4][4];
        #pragma unroll
        for (int r = 0; r < NR; r++)
            #pragma unroll
            for (int c = 0; c < 4; c++) acc[r][c] = 0ull;
        {
            ulonglong2 wA = WQ[0], wB = WQ[160], wC = WQ[320], wD = WQ[480];
            for (int kp = 0; kp < 64; kp++) {
                const ulonglong2* Wn = WQ + (kp + 1) * 640;
                ulonglong2 nA = Wn[0], nB = Wn[160], nC = Wn[320], nD = Wn[480];
                #pragma unroll
                for (int r = 0; r < NR; r++) {
                    ulonglong2 h01 = Hb[r * 128 + kp];
                    fma2(acc[r][0], h01.x, wA.x); fma2(acc[r][1], h01.x, wA.y);
                    fma2(acc[r][2], h01.x, wB.x); fma2(acc[r][3], h01.x, wB.y);
                    fma2(acc[r][0], h01.y, wC.x); fma2(acc[r][1], h01.y, wC.y);
                    fma2(acc[r][2], h01.y, wD.x); fma2(acc[r][3], h01.y, wD.y);
                }
                wA = nA; wB = nB; wC = nC; wD = nD;
            }
        }
        // store partials of the OTHER half's epilogue rows
        {
            #pragma unroll
            for (int rr = 0; rr < 2; rr++) {
                int orow = 2 * (1 - kh) + rr;
                if (orow < NR) {
                    ulonglong2* P = (ulonglong2*)&part[((kh * 2 + rr) * 160 + qi) * 4];
                    P[0] = make_ulonglong2(acc[orow][0], acc[orow][1]);
                    P[1] = make_ulonglong2(acc[orow][2], acc[orow][3]);
                }
            }
        }
        __syncthreads();

        // ===== S1 reduce + epilogue (rows r0e, r0e+1 if < NR) =====
        {
            #pragma unroll
            for (int rr = 0; rr < 2; rr++) {
                int row = r0e + rr;
                if (row >= NR) continue;
                const ulonglong2* P = (const ulonglong2*)
                    &part[(((1 - kh) * 2 + rr) * 160 + qi) * 4];
                ulonglong2 p0 = P[0], p1 = P[1];
                u64 f0 = add2(acc[row][0], p0.x);
                u64 f1 = add2(acc[row][1], p0.y);
                u64 f2 = add2(acc[row][2], p1.x);
                u64 f3 = add2(acc[row][3], p1.y);
                float2 a0 = upk(f0), a1 = upk(f1), a2 = upk(f2), a3 = upk(f3);
                if (n0 < 256) {
                    ulonglong2* E = (ulonglong2*)(G1p + row * 256 + n0);
                    E[0] = make_ulonglong2(pk2(eluf(a0.x + b1a.x)), pk2(eluf(a0.y + b1a.y)));
                    E[1] = make_ulonglong2(pk2(eluf(a1.x + b1a.z)), pk2(eluf(a1.y + b1a.w)));
                    E[2] = make_ulonglong2(pk2(eluf(a2.x + b1b.x)), pk2(eluf(a2.y + b1b.y)));
                    E[3] = make_ulonglong2(pk2(eluf(a3.x + b1b.z)), pk2(eluf(a3.y + b1b.w)));
                } else if (n0 < 512) {
                    float4 q0 = *(const float4*)&qcur[row * 256 + (n0 - 256)];
                    float4 q1 = *(const float4*)&qcur[row * 256 + (n0 - 252)];
                    ulonglong2* E = (ulonglong2*)(G1q + row * 256 + (n0 - 256));
                    E[0] = make_ulonglong2(pk2(eluf(a0.x + q0.x)), pk2(eluf(a0.y + q0.y)));
                    E[1] = make_ulonglong2(pk2(eluf(a1.x + q0.z)), pk2(eluf(a1.y + q0.w)));
                    E[2] = make_ulonglong2(pk2(eluf(a2.x + q1.x)), pk2(eluf(a2.y + q1.y)));
                    E[3] = make_ulonglong2(pk2(eluf(a3.x + q1.z)), pk2(eluf(a3.y + q1.w)));
                } else {
                    *(float4*)&Gh[row * 768 + (n0 - 512)] =
                        make_float4(a0.x + b1a.x, a0.y + b1a.y, a1.x + b1a.z, a1.y + b1a.w);
                    *(float4*)&Gh[row * 768 + (n0 - 508)] =
                        make_float4(a2.x + b1b.x, a2.y + b1b.y, a3.x + b1b.z, a3.y + b1b.w);
                }
            }
        }
        __syncthreads();

        // ==== S2 partials (p<256); p>=256: h-out + next-q1emb prefetch ====
        if (p < 256) {
            const ulonglong2* INv = (const ulonglong2*)((s2_u < 32) ? G1p : G1q);
            u64 a4[4];
            #pragma unroll
            for (int r = 0; r < NR; r++) a4[r] = 0ull;
            int kbase = s2_kb * 32;
            #pragma unroll 4
            for (int qq2 = 0; qq2 < 32; qq2++) {
                int kpg = kbase + qq2;
                ulonglong2 w = WPQ[kpg * 64 + s2_u];
                #pragma unroll
                for (int r = 0; r < NR; r++) {
                    ulonglong2 iv = INv[r * 128 + kpg];
                    fma2(a4[r], iv.x, w.x);
                    fma2(a4[r], iv.y, w.y);
                }
            }
            #pragma unroll
            for (int r = 0; r < NR; r++)
                part[(s2_kb * 4 + r) * 64 + s2_u] = a4[r];
        } else {
            int idx = p - 256;   // 0..63
            #pragma unroll
            for (int j = 0; j < 16; j++) {
                int i = idx + j * 64, r = i >> 8, d = i & 255;
                if (r < NR)
                    __stcs(&out[(long)(b0 + r) * 53248 + tt * 416 + d], hF[2 * i]);
            }
            if (tt + 1 < Tn) {
                #pragma unroll
                for (int j = 0; j < 4; j++) {
                    int i = idx + j * 64;            // 0..255 float4 chunks
                    int r = i >> 6, c4 = (i & 63) * 4;
                    if (r < NR)
                        *(float4*)&qnxt[r * 256 + c4] =
                            __ldcs((const float4*)&g_q1emb[((long)(b0 + r) * Tn + tt + 1) * 256 + c4]);
                }
            }
        }
        __syncthreads();

        // ===== Fused S2 reduce: stats -> out, z via shfl, x2 =====
        if (p < 256) {
            int r = p >> 6;      // warp-uniform (2 warps per r)
            if (r < NR) {
                u64 s = part[r * 64 + s2_u];
                #pragma unroll
                for (int kb = 1; kb < 4; kb++)
                    s = add2(s, part[(kb * 4 + r) * 64 + s2_u]);
                float2 v = upk(s);
                v.x += s2_b.x; v.y += s2_b.y;
                if (s2_c >= 16) { v.x = __expf(clipf(v.x)); v.y = __expf(clipf(v.y)); }
                long ob = (long)(b0 + r) * 53248 + tt * 416;
                __stcs((float2*)&out[ob + 288 + (s2_u < 32 ? 0 : 64) + 2 * s2_c], v);
                if (s2_u >= 32) {   // Q warps: swap qm<->qs across half-warps
                    float ox = __shfl_xor_sync(0xffffffffu, v.x, 16);
                    float oy = __shfl_xor_sync(0xffffffffu, v.y, 16);
                    if (s2_c < 16) {
                        float z0 = fmaf(ox, eps.x, v.x);
                        float z1 = fmaf(oy, eps.y, v.y);
                        *(ulonglong2*)&x2[r * 40 + 2 * s2_c] =
                            make_ulonglong2(pk2(z0), pk2(z1));
                        __stcs((float2*)&out[ob + 256 + 2 * s2_c], make_float2(z0, z1));
                    }
                }
            }
        } else if (p >= 288) {
            int qq = p - 288, r = qq >> 3, j = qq & 7;
            if (r < NR) x2[r * 40 + 32 + j] = pk2(av);
        }
        __syncthreads();

        // ===== S3: gi = x @ W_ih (384 col-pairs over 320 threads) =====
        for (int cp = p; cp < 384; cp += SQ_T) {
            float2 bih = *(const float2*)&b_ih[2 * cp];
            u64 a3[4];
            #pragma unroll
            for (int r = 0; r < NR; r++) a3[r] = 0ull;
            #pragma unroll 4
            for (int kp = 0; kp < 20; kp++) {
                ulonglong2 w = WI[kp * 384 + cp];
                #pragma unroll
                for (int r = 0; r < NR; r++) {
                    ulonglong2 iv = X2v[r * 20 + kp];
                    fma2(a3[r], iv.x, w.x);
                    fma2(a3[r], iv.y, w.y);
                }
            }
            #pragma unroll
            for (int r = 0; r < NR; r++) {
                float2 a0 = upk(a3[r]);
                *(float2*)&gi[r * 768 + 2 * cp] = make_float2(a0.x + bih.x, a0.y + bih.y);
            }
        }
        __syncthreads();

        // ===== S4: GRU gates -> new h =====
        for (int i = p; i < 256 * NR; i += SQ_T) {
            int r = i >> 8, d = i & 255;
            float gir = gi[r * 768 + d];
            float giz = gi[r * 768 + 256 + d];
            float gin = gi[r * 768 + 512 + d];
            float ghr = Gh[r * 768 + d];
            float ghz = Gh[r * 768 + 256 + d];
            float ghn = Gh[r * 768 + 512 + d];
            float rg = sigf(gir + ghr);
            float ug = sigf(giz + ghz);
            float ng = tanf_(gin + rg * ghn);
            float ho = hF[2 * i];
            h2[i] = pk2((1.f - ug) * ng + ug * ho);
        }
        __syncthreads();
    }
}

__global__ void __launch_bounds__(SQ_T, 2) seq_kernel(
    const float* __restrict__ act,  const float* __restrict__ noise,
    const float* __restrict__ b_p1, const float* __restrict__ b_hh,
    const float* __restrict__ b_p2, const float* __restrict__ b_q2,
    const float* __restrict__ b_ih, float* __restrict__ out)
{
    extern __shared__ u64 smu[];
    int bid = blockIdx.x;
    if (bid < 148)
        seq_body<4>(4 * bid, smu, act, noise, b_p1, b_hh, b_p2, b_q2, b_ih, out);
    else if (bid < 284)
        seq_body<3>(592 + 3 * (bid - 148), smu, act, noise, b_p1, b_hh, b_p2, b_q2, b_ih, out);
    else
        seq_body<2>(1000 + 2 * (bid - 284), smu, act, noise, b_p1, b_hh, b_p2, b_q2, b_ih, out);
}

// ---------------------------------------------------------------------------
extern "C" void kernel_launch(void* const* d_in, const int* in_sizes, int n_in,
                              void* d_out, int out_size)
{
    const float* obs = (const float*)d_in[0];
    const float* act = (const float*)d_in[1];
    const float* noi = (const float*)d_in[2];
    const float* We1 = (const float*)d_in[3];
    const float* be1 = (const float*)d_in[4];
    const float* We2 = (const float*)d_in[5];
    const float* be2 = (const float*)d_in[6];
    const float* Wih = (const float*)d_in[7];
    const float* Whh = (const float*)d_in[8];
    const float* bih = (const float*)d_in[9];
    const float* bhh = (const float*)d_in[10];
    const float* Wp1 = (const float*)d_in[11];
    const float* bp1 = (const float*)d_in[12];
    const float* Wp2 = (const float*)d_in[13];
    const float* bp2 = (const float*)d_in[14];
    const float* Wq1 = (const float*)d_in[15];
    const float* bq1 = (const float*)d_in[16];
    const float* Wq2 = (const float*)d_in[17];
    const float* bq2 = (const float*)d_in[18];
    float* out = (float*)d_out;

    cudaFuncSetAttribute(emb_kernel, cudaFuncAttributeMaxDynamicSharedMemorySize, EMB_SMEM);
    cudaFuncSetAttribute(seq_kernel, cudaFuncAttributeMaxDynamicSharedMemorySize, SEQ_SMEM);

    prep_kernel<<<64, 256>>>(Wp1, Wq1, Whh, Wih, Wp2, Wq2, We1, We2);
    emb_kernel<<<(Bsz * Tn) / 32, EMB_T, EMB_SMEM>>>(obs, be1, be2, bq1);
    seq_kernel<<<296, SQ_T, SEQ_SMEM>>>(act, noi, bp1, bhh, bp2, bq2, bih, out);
}